// round 4
// baseline (speedup 1.0000x reference)
#include <cuda_runtime.h>
#include <cstdint>

#define KTOP 2048
#define DD 128
#define NBINS 65536
#define CAND_MAX 8192
#define TPB 512
#define NB_CAP 1024

// ---- static scratch (no allocations allowed) ----
__device__ unsigned int g_hist[NBINS];
__device__ unsigned int g_chist[256];
__device__ float g_y[500224];
__device__ unsigned int g_tbin;
__device__ unsigned int g_cnt;
__device__ __align__(16) unsigned long long g_cand[CAND_MAX];
__device__ float g_tval[KTOP];
__device__ int g_tidx[KTOP];
__device__ unsigned int g_bar_count;
__device__ volatile unsigned int g_bar_gen;

// monotonic unsigned key for f32 ordering
__device__ __forceinline__ unsigned int fkey(float f) {
    unsigned int u = __float_as_uint(f);
    return (u & 0x80000000u) ? ~u : (u | 0x80000000u);
}
__device__ __forceinline__ float dot4(float4 a, float4 b) {
    return a.x * b.x + a.y * b.y + a.z * b.z + a.w * b.w;
}

// software grid barrier (all blocks co-resident by construction)
__device__ __forceinline__ void grid_bar(int nb) {
    __threadfence();
    __syncthreads();
    if (threadIdx.x == 0) {
        unsigned int gen = g_bar_gen;
        if (atomicAdd(&g_bar_count, 1u) == (unsigned int)(nb - 1)) {
            g_bar_count = 0u;
            __threadfence();
            g_bar_gen = gen + 1u;
        } else {
            while (g_bar_gen == gen) { }
        }
    }
    __syncthreads();
}

__device__ __forceinline__ void try_push(float y, int i, unsigned int tb) {
    unsigned int key = fkey(y);
    if ((key >> 16) >= tb) {
        unsigned int pos = atomicAdd(&g_cnt, 1u);
        if (pos < CAND_MAX) {
            // value-descending major, index-ascending minor
            g_cand[pos] = ((unsigned long long)key << 32) |
                          (unsigned long long)(~(unsigned int)i);
        }
    }
}

__global__ void __launch_bounds__(TPB, 2)
mega(const float* __restrict__ x, const float* __restrict__ p,
     float* __restrict__ out, int n, int nb)
{
    const int tid = threadIdx.x;
    const int lane = tid & 31;
    const int l8 = lane & 7;
    const int grp = lane >> 3;
    const int gtid = blockIdx.x * TPB + tid;
    const int gthreads = nb * TPB;
    const int wid = gtid >> 5;
    const int nw = gthreads >> 5;

    __shared__ unsigned long long sk[2048];     // phase-4 key chunk (16 KB)
    __shared__ unsigned int ss[257];            // phase-2 scans
    __shared__ unsigned int s_above;
    __shared__ int s_cb;

    // ---- phase 0: each warp self-computes norm; p slice in registers ----
    const float4* __restrict__ p4 = reinterpret_cast<const float4*>(p);
    float4 q0 = p4[l8], q1 = p4[l8 + 8], q2 = p4[l8 + 16], q3 = p4[l8 + 24];
    float s2 = (dot4(q0, q0) + dot4(q1, q1)) + (dot4(q2, q2) + dot4(q3, q3));
    s2 += __shfl_xor_sync(0xffffffffu, s2, 1);
    s2 += __shfl_xor_sync(0xffffffffu, s2, 2);
    s2 += __shfl_xor_sync(0xffffffffu, s2, 4);
    const float inv = 1.0f / sqrtf(s2);

    // ---- phase 1: coalesced dot (8 lanes per row, 4 rows per warp-iter) ----
    const float4* __restrict__ x4 = reinterpret_cast<const float4*>(x);
    for (int r0 = wid * 4; r0 < n; r0 += nw * 4) {
        int r = r0 + grp;
        bool h = (r < n);
        float4 v0, v1, v2, v3;
        if (h) {
            const float4* xr = x4 + (size_t)r * 32 + l8;
            v0 = xr[0]; v1 = xr[8]; v2 = xr[16]; v3 = xr[24];
        } else {
            v0 = v1 = v2 = v3 = make_float4(0.f, 0.f, 0.f, 0.f);
        }
        float s = (dot4(v0, q0) + dot4(v1, q1)) + (dot4(v2, q2) + dot4(v3, q3));
        s += __shfl_xor_sync(0xffffffffu, s, 1);
        s += __shfl_xor_sync(0xffffffffu, s, 2);
        s += __shfl_xor_sync(0xffffffffu, s, 4);
        if (l8 == 0 && h) {
            float y = s * inv;
            g_y[r] = y;
            unsigned int k = fkey(y);
            atomicAdd(&g_hist[k >> 16], 1u);
            atomicAdd(&g_chist[k >> 24], 1u);
        }
    }
    grid_bar(nb);

    // ---- phase 2: block 0 finds threshold bin (coarse -> fine) ----
    if (blockIdx.x == 0) {
        // coarse suffix scan (256 bins)
        if (tid < 256) ss[tid] = g_chist[tid];
        __syncthreads();
        for (int off = 1; off < 256; off <<= 1) {
            unsigned int v = 0;
            if (tid < 256 && tid + off < 256) v = ss[tid + off];
            __syncthreads();
            if (tid < 256) ss[tid] += v;
            __syncthreads();
        }
        if (tid < 256) {
            unsigned int incl = ss[tid];
            unsigned int nxt = (tid < 255) ? ss[tid + 1] : 0u;
            if (incl >= KTOP && nxt < KTOP) { s_cb = tid; s_above = nxt; }
        }
        __syncthreads();
        int cb = s_cb;
        unsigned int above = s_above;
        // fine suffix scan within the coarse bin (256 bins)
        if (tid < 256) ss[tid] = g_hist[cb * 256 + tid];
        __syncthreads();
        for (int off = 1; off < 256; off <<= 1) {
            unsigned int v = 0;
            if (tid < 256 && tid + off < 256) v = ss[tid + off];
            __syncthreads();
            if (tid < 256) ss[tid] += v;
            __syncthreads();
        }
        if (tid < 256) {
            unsigned int incl = ss[tid] + above;
            unsigned int nxt = ((tid < 255) ? ss[tid + 1] : 0u) + above;
            if (incl >= KTOP && nxt < KTOP)
                g_tbin = (unsigned int)(cb * 256 + tid);
        }
    }
    grid_bar(nb);

    // ---- phase 3: compact candidates (whole grid, one float4/thread) ----
    {
        unsigned int tb = g_tbin;
        int n4 = n >> 2;
        const float4* __restrict__ y4 = reinterpret_cast<const float4*>(g_y);
        for (int i = gtid; i < n4; i += gthreads) {
            float4 v = y4[i];
            try_push(v.x, i * 4 + 0, tb);
            try_push(v.y, i * 4 + 1, tb);
            try_push(v.z, i * 4 + 2, tb);
            try_push(v.w, i * 4 + 3, tb);
        }
        if (gtid == 0) {
            for (int j = n & ~3; j < n; j++) try_push(g_y[j], j, tb);
        }
    }
    grid_bar(nb);

    // ---- phase 4: exact rank via smem-staged chunks ----
    {
        int C = (int)min(g_cnt, (unsigned int)CAND_MAX);
        if (blockIdx.x * TPB < C) {
            int j = gtid;
            unsigned long long pk = (j < C) ? g_cand[j] : ~0ull;
            int rank = 0;
            for (int base = 0; base < C; base += 2048) {
                int m = C - base; if (m > 2048) m = 2048;
                for (int i = tid; i < m; i += TPB) sk[i] = g_cand[base + i];
                __syncthreads();
                #pragma unroll 8
                for (int i = 0; i < m; i++) rank += (sk[i] > pk);
                __syncthreads();
            }
            if (j < C && rank < KTOP) {
                unsigned int key = (unsigned int)(pk >> 32);
                unsigned int u = (key & 0x80000000u) ? (key ^ 0x80000000u) : ~key;
                g_tval[rank] = __uint_as_float(u);
                g_tidx[rank] = (int)(~(unsigned int)(pk & 0xFFFFFFFFull));
            }
        }
    }
    grid_bar(nb);

    // ---- phase 5: gather + tanh scale; restore state for next replay ----
    float4* __restrict__ o4 = reinterpret_cast<float4*>(out);
    for (int w = wid; w < KTOP; w += nw) {
        int idx = g_tidx[w];
        float t = tanhf(g_tval[w]);
        float4 v = x4[(size_t)idx * 32 + lane];
        o4[(size_t)w * 32 + lane] = make_float4(v.x * t, v.y * t, v.z * t, v.w * t);
    }
    for (int i = gtid; i < NBINS; i += gthreads) g_hist[i] = 0u;
    if (gtid < 256) g_chist[gtid] = 0u;
    if (gtid == 0) g_cnt = 0u;
}

extern "C" void kernel_launch(void* const* d_in, const int* in_sizes, int n_in,
                              void* d_out, int out_size) {
    const float* x = (const float*)d_in[0];
    const float* p = (const float*)d_in[1];
    int n = in_sizes[0] / DD;

    int dev = 0;
    cudaGetDevice(&dev);
    int sm = 0;
    cudaDeviceGetAttribute(&sm, cudaDevAttrMultiProcessorCount, dev);
    int bpsm = 0;
    cudaOccupancyMaxActiveBlocksPerMultiprocessor(&bpsm, mega, TPB, 0);
    if (bpsm < 1) bpsm = 1;
    int nb = sm * bpsm;
    if (nb > NB_CAP) nb = NB_CAP;

    mega<<<nb, TPB>>>(x, p, (float*)d_out, n, nb);
}

// round 5
// speedup vs baseline: 2.7038x; 2.7038x over previous
#include <cuda_runtime.h>
#include <cstdint>

#define KTOP 2048
#define DD 128
#define HBINS 8192            // 13-bit key prefix
#define HSHIFT 19             // 32 - 13
#define CAND_MAX 4608
#define TPB 512
#define NB_CAP 1024

// ---- static scratch (no allocations allowed) ----
__device__ unsigned int g_hist[HBINS];
__device__ float g_y[500224];
__device__ unsigned int g_tbin;
__device__ unsigned int g_cnt;
__device__ __align__(16) unsigned long long g_cand[CAND_MAX];
__device__ float g_tval[KTOP];
__device__ int g_tidx[KTOP];
__device__ unsigned int g_bar_count;
__device__ volatile unsigned int g_bar_gen;

// monotonic unsigned key for f32 ordering
__device__ __forceinline__ unsigned int fkey(float f) {
    unsigned int u = __float_as_uint(f);
    return (u & 0x80000000u) ? ~u : (u | 0x80000000u);
}
__device__ __forceinline__ float dot4(float4 a, float4 b) {
    return a.x * b.x + a.y * b.y + a.z * b.z + a.w * b.w;
}

// software grid barrier (all blocks co-resident by construction)
__device__ __forceinline__ void grid_bar(int nb) {
    __threadfence();
    __syncthreads();
    if (threadIdx.x == 0) {
        unsigned int gen = g_bar_gen;
        if (atomicAdd(&g_bar_count, 1u) == (unsigned int)(nb - 1)) {
            g_bar_count = 0u;
            __threadfence();
            g_bar_gen = gen + 1u;
        } else {
            while (g_bar_gen == gen) { }
        }
    }
    __syncthreads();
}

__device__ __forceinline__ void try_push(float y, int i, unsigned int tb) {
    unsigned int key = fkey(y);
    if ((key >> HSHIFT) >= tb) {
        unsigned int pos = atomicAdd(&g_cnt, 1u);
        if (pos < CAND_MAX) {
            // value-descending major, index-ascending minor
            g_cand[pos] = ((unsigned long long)key << 32) |
                          (unsigned long long)(~(unsigned int)i);
        }
    }
}

__global__ void __launch_bounds__(TPB, 2)
mega(const float* __restrict__ x, const float* __restrict__ p,
     float* __restrict__ out, int n, int nb)
{
    const int tid = threadIdx.x;
    const int lane = tid & 31;
    const int l8 = lane & 7;
    const int grp = lane >> 3;
    const int gtid = blockIdx.x * TPB + tid;
    const int gthreads = nb * TPB;
    const int wid = gtid >> 5;
    const int nw = gthreads >> 5;

    // 36 KB union: phase-1 smem histogram (8192 u32) / phase-4 key cache (4608 u64)
    __shared__ __align__(16) unsigned char sbuf[36864];
    unsigned int* shist = reinterpret_cast<unsigned int*>(sbuf);
    unsigned long long* sk = reinterpret_cast<unsigned long long*>(sbuf);
    __shared__ unsigned int ss[512];

    // ---- phase 0: norm (per-warp, registers only) ----
    const float4* __restrict__ p4 = reinterpret_cast<const float4*>(p);
    float4 q0 = p4[l8], q1 = p4[l8 + 8], q2 = p4[l8 + 16], q3 = p4[l8 + 24];
    float s2 = (dot4(q0, q0) + dot4(q1, q1)) + (dot4(q2, q2) + dot4(q3, q3));
    s2 += __shfl_xor_sync(0xffffffffu, s2, 1);
    s2 += __shfl_xor_sync(0xffffffffu, s2, 2);
    s2 += __shfl_xor_sync(0xffffffffu, s2, 4);
    const float inv = 1.0f / sqrtf(s2);

    // ---- phase 1: coalesced dot, private smem histogram ----
    for (int i = tid; i < HBINS; i += TPB) shist[i] = 0u;
    __syncthreads();

    const float4* __restrict__ x4 = reinterpret_cast<const float4*>(x);
    for (int r0 = wid * 8; r0 < n; r0 += nw * 8) {
        int rA = r0 + grp;
        int rB = r0 + 4 + grp;
        bool hA = rA < n, hB = rB < n;
        float4 z = make_float4(0.f, 0.f, 0.f, 0.f);
        float4 a0 = z, a1 = z, a2 = z, a3 = z, b0 = z, b1 = z, b2 = z, b3 = z;
        if (hA) {
            const float4* xr = x4 + (size_t)rA * 32 + l8;
            a0 = xr[0]; a1 = xr[8]; a2 = xr[16]; a3 = xr[24];
        }
        if (hB) {
            const float4* xr = x4 + (size_t)rB * 32 + l8;
            b0 = xr[0]; b1 = xr[8]; b2 = xr[16]; b3 = xr[24];
        }
        float sA = (dot4(a0, q0) + dot4(a1, q1)) + (dot4(a2, q2) + dot4(a3, q3));
        float sB = (dot4(b0, q0) + dot4(b1, q1)) + (dot4(b2, q2) + dot4(b3, q3));
        sA += __shfl_xor_sync(0xffffffffu, sA, 1);
        sB += __shfl_xor_sync(0xffffffffu, sB, 1);
        sA += __shfl_xor_sync(0xffffffffu, sA, 2);
        sB += __shfl_xor_sync(0xffffffffu, sB, 2);
        sA += __shfl_xor_sync(0xffffffffu, sA, 4);
        sB += __shfl_xor_sync(0xffffffffu, sB, 4);
        if (l8 == 0) {
            if (hA) {
                float yA = sA * inv;
                g_y[rA] = yA;
                atomicAdd(&shist[fkey(yA) >> HSHIFT], 1u);
            }
            if (hB) {
                float yB = sB * inv;
                g_y[rB] = yB;
                atomicAdd(&shist[fkey(yB) >> HSHIFT], 1u);
            }
        }
    }
    __syncthreads();
    for (int i = tid; i < HBINS; i += TPB) {
        unsigned int v = shist[i];
        if (v) atomicAdd(&g_hist[i], v);
    }
    grid_bar(nb);

    // ---- phase 2: block 0 finds threshold bin (16 bins/thread + suffix scan) ----
    if (blockIdx.x == 0) {
        const uint4* h4 = reinterpret_cast<const uint4*>(g_hist) + tid * 4;
        uint4 a = h4[0], b = h4[1], c = h4[2], d = h4[3];
        unsigned int part = a.x + a.y + a.z + a.w + b.x + b.y + b.z + b.w
                          + c.x + c.y + c.z + c.w + d.x + d.y + d.z + d.w;
        ss[tid] = part;
        __syncthreads();
        for (int off = 1; off < 512; off <<= 1) {
            unsigned int v = (tid + off < 512) ? ss[tid + off] : 0u;
            __syncthreads();
            ss[tid] += v;
            __syncthreads();
        }
        unsigned int incl = ss[tid];
        unsigned int nxt = (tid < 511) ? ss[tid + 1] : 0u;
        if (incl >= KTOP && nxt < KTOP) {
            unsigned int acc = nxt;
            for (int bi = tid * 16 + 15; bi >= tid * 16; bi--) {
                acc += g_hist[bi];
                if (acc >= KTOP) { g_tbin = (unsigned int)bi; break; }
            }
        }
    }
    grid_bar(nb);

    // ---- phase 3: compact candidates (whole grid, one float4/thread) ----
    {
        unsigned int tb = g_tbin;
        int n4 = n >> 2;
        const float4* __restrict__ y4 = reinterpret_cast<const float4*>(g_y);
        for (int i = gtid; i < n4; i += gthreads) {
            float4 v = y4[i];
            try_push(v.x, i * 4 + 0, tb);
            try_push(v.y, i * 4 + 1, tb);
            try_push(v.z, i * 4 + 2, tb);
            try_push(v.w, i * 4 + 3, tb);
        }
        if (gtid == 0) {
            for (int j = n & ~3; j < n; j++) try_push(g_y[j], j, tb);
        }
    }
    grid_bar(nb);

    // ---- phase 4: exact rank; 64 candidates/block, smem-cached keys ----
    {
        int C = (int)min(g_cnt, (unsigned int)CAND_MAX);
        int nactive = (C + 63) >> 6;
        if (blockIdx.x < nactive) {
            for (int i = tid; i < C; i += TPB) sk[i] = g_cand[i];
            __syncthreads();
            int j = blockIdx.x * 64 + tid;
            if (tid < 64 && j < C) {
                unsigned long long pk = sk[j];
                int rank = 0;
                const ulonglong2* s2k = reinterpret_cast<const ulonglong2*>(sk);
                int C2 = C >> 1;
                int i = 0;
                for (; i + 4 <= C2; i += 4) {
                    ulonglong2 v0 = s2k[i + 0];
                    ulonglong2 v1 = s2k[i + 1];
                    ulonglong2 v2 = s2k[i + 2];
                    ulonglong2 v3 = s2k[i + 3];
                    rank += (v0.x > pk) + (v0.y > pk);
                    rank += (v1.x > pk) + (v1.y > pk);
                    rank += (v2.x > pk) + (v2.y > pk);
                    rank += (v3.x > pk) + (v3.y > pk);
                }
                for (; i < C2; i++) {
                    ulonglong2 v = s2k[i];
                    rank += (v.x > pk) + (v.y > pk);
                }
                if (C & 1) rank += (sk[C - 1] > pk);
                if (rank < KTOP) {
                    unsigned int key = (unsigned int)(pk >> 32);
                    unsigned int u = (key & 0x80000000u) ? (key ^ 0x80000000u) : ~key;
                    g_tval[rank] = __uint_as_float(u);
                    g_tidx[rank] = (int)(~(unsigned int)(pk & 0xFFFFFFFFull));
                }
            }
        }
    }
    grid_bar(nb);

    // ---- phase 5: gather + tanh; restore global state for next replay ----
    float4* __restrict__ o4 = reinterpret_cast<float4*>(out);
    for (int w = wid; w < KTOP; w += nw) {
        int idx = g_tidx[w];
        float t = tanhf(g_tval[w]);
        float4 v = x4[(size_t)idx * 32 + lane];
        o4[(size_t)w * 32 + lane] = make_float4(v.x * t, v.y * t, v.z * t, v.w * t);
    }
    for (int i = gtid; i < HBINS; i += gthreads) g_hist[i] = 0u;
    if (gtid == 0) g_cnt = 0u;
}

extern "C" void kernel_launch(void* const* d_in, const int* in_sizes, int n_in,
                              void* d_out, int out_size) {
    const float* x = (const float*)d_in[0];
    const float* p = (const float*)d_in[1];
    int n = in_sizes[0] / DD;

    int dev = 0;
    cudaGetDevice(&dev);
    int sm = 0;
    cudaDeviceGetAttribute(&sm, cudaDevAttrMultiProcessorCount, dev);
    int bpsm = 0;
    cudaOccupancyMaxActiveBlocksPerMultiprocessor(&bpsm, mega, TPB, 0);
    if (bpsm < 1) bpsm = 1;
    int nb = sm * bpsm;
    if (nb > NB_CAP) nb = NB_CAP;

    mega<<<nb, TPB>>>(x, p, (float*)d_out, n, nb);
}

// round 6
// speedup vs baseline: 3.0969x; 1.1454x over previous
#include <cuda_runtime.h>
#include <cstdint>

#define KTOP 2048
#define DD 128
#define HBINS 8192            // 13-bit key prefix
#define HSHIFT 19             // 32 - 13
#define CAND_MAX 4608
#define TPB 512
#define NB_CAP 1024

// ---- static scratch (no allocations allowed) ----
__device__ unsigned int g_hist[HBINS];
__device__ float g_y[500224];
__device__ unsigned int g_cnt;
__device__ __align__(16) unsigned long long g_cand[CAND_MAX];
__device__ float g_tval[KTOP];
__device__ int g_tidx[KTOP];
__device__ unsigned int g_bar_count;
__device__ volatile unsigned int g_bar_gen;

// monotonic unsigned key for f32 ordering
__device__ __forceinline__ unsigned int fkey(float f) {
    unsigned int u = __float_as_uint(f);
    return (u & 0x80000000u) ? ~u : (u | 0x80000000u);
}
__device__ __forceinline__ float dot4(float4 a, float4 b) {
    return a.x * b.x + a.y * b.y + a.z * b.z + a.w * b.w;
}

// software grid barrier (all blocks co-resident by construction)
__device__ __forceinline__ void grid_bar(int nb) {
    __threadfence();
    __syncthreads();
    if (threadIdx.x == 0) {
        unsigned int gen = g_bar_gen;
        if (atomicAdd(&g_bar_count, 1u) == (unsigned int)(nb - 1)) {
            g_bar_count = 0u;
            __threadfence();
            g_bar_gen = gen + 1u;
        } else {
            while (g_bar_gen == gen) { __nanosleep(64); }
        }
    }
    __syncthreads();
}

__device__ __forceinline__ void try_push(float y, int i, unsigned int tb) {
    unsigned int key = fkey(y);
    if ((key >> HSHIFT) >= tb) {
        unsigned int pos = atomicAdd(&g_cnt, 1u);
        if (pos < CAND_MAX) {
            // value-descending major, index-ascending minor
            g_cand[pos] = ((unsigned long long)key << 32) |
                          (unsigned long long)(~(unsigned int)i);
        }
    }
}

__global__ void __launch_bounds__(TPB, 2)
mega(const float* __restrict__ x, const float* __restrict__ p,
     float* __restrict__ out, int n, int nb)
{
    const int tid = threadIdx.x;
    const int lane = tid & 31;
    const int l8 = lane & 7;
    const int grp = lane >> 3;
    const int gtid = blockIdx.x * TPB + tid;
    const int gthreads = nb * TPB;
    const int wid = gtid >> 5;
    const int nw = gthreads >> 5;

    // union: phase-1 smem histogram (8192 u32 = 32 KB) / phase-4 keys (4608 u64 = 36.9 KB)
    __shared__ __align__(16) unsigned char sbuf[36864];
    unsigned int* shist = reinterpret_cast<unsigned int*>(sbuf);
    unsigned long long* sk = reinterpret_cast<unsigned long long*>(sbuf);
    __shared__ unsigned int ss[512];
    __shared__ unsigned int s_tbin;

    // ---- phase 0: norm (per-warp, registers only) ----
    const float4* __restrict__ p4 = reinterpret_cast<const float4*>(p);
    float4 q0 = p4[l8], q1 = p4[l8 + 8], q2 = p4[l8 + 16], q3 = p4[l8 + 24];
    float s2 = (dot4(q0, q0) + dot4(q1, q1)) + (dot4(q2, q2) + dot4(q3, q3));
    s2 += __shfl_xor_sync(0xffffffffu, s2, 1);
    s2 += __shfl_xor_sync(0xffffffffu, s2, 2);
    s2 += __shfl_xor_sync(0xffffffffu, s2, 4);
    const float inv = 1.0f / sqrtf(s2);

    // ---- phase 1: coalesced dot (branchless main loop), private smem hist ----
    for (int i = tid; i < HBINS; i += TPB) shist[i] = 0u;
    __syncthreads();

    const float4* __restrict__ x4 = reinterpret_cast<const float4*>(x);
    const int n8 = n & ~7;
    for (int r0 = wid * 8; r0 < n8; r0 += nw * 8) {
        int rA = r0 + grp;
        int rB = rA + 4;
        const float4* xa = x4 + (size_t)rA * 32 + l8;
        const float4* xb = x4 + (size_t)rB * 32 + l8;
        float4 a0 = __ldcs(xa + 0), a1 = __ldcs(xa + 8),
               a2 = __ldcs(xa + 16), a3 = __ldcs(xa + 24);
        float4 b0 = __ldcs(xb + 0), b1 = __ldcs(xb + 8),
               b2 = __ldcs(xb + 16), b3 = __ldcs(xb + 24);
        float sA = (dot4(a0, q0) + dot4(a1, q1)) + (dot4(a2, q2) + dot4(a3, q3));
        float sB = (dot4(b0, q0) + dot4(b1, q1)) + (dot4(b2, q2) + dot4(b3, q3));
        sA += __shfl_xor_sync(0xffffffffu, sA, 1);
        sB += __shfl_xor_sync(0xffffffffu, sB, 1);
        sA += __shfl_xor_sync(0xffffffffu, sA, 2);
        sB += __shfl_xor_sync(0xffffffffu, sB, 2);
        sA += __shfl_xor_sync(0xffffffffu, sA, 4);
        sB += __shfl_xor_sync(0xffffffffu, sB, 4);
        if (l8 == 0) {
            float yA = sA * inv;
            float yB = sB * inv;
            g_y[rA] = yA;
            g_y[rB] = yB;
            atomicAdd(&shist[fkey(yA) >> HSHIFT], 1u);
            atomicAdd(&shist[fkey(yB) >> HSHIFT], 1u);
        }
    }
    // tail rows [n8, n): block 0 / warp 0, full-width dot
    if (blockIdx.x == 0 && tid < 32 && n8 < n) {
        float4 pl = p4[lane];
        for (int r = n8; r < n; r++) {
            float4 v = x4[(size_t)r * 32 + lane];
            float s = dot4(v, pl);
            #pragma unroll
            for (int o = 16; o; o >>= 1) s += __shfl_xor_sync(0xffffffffu, s, o);
            if (lane == 0) {
                float y = s * inv;
                g_y[r] = y;
                atomicAdd(&shist[fkey(y) >> HSHIFT], 1u);
            }
        }
    }
    __syncthreads();
    for (int i = tid; i < HBINS; i += TPB) {
        unsigned int v = shist[i];
        if (v) atomicAdd(&g_hist[i], v);
    }
    grid_bar(nb);

    // ---- phase 2 (every block, redundant): find threshold bin locally ----
    {
        const uint4* h4 = reinterpret_cast<const uint4*>(g_hist) + tid * 4;
        uint4 a = h4[0], b = h4[1], c = h4[2], d = h4[3];
        unsigned int part = a.x + a.y + a.z + a.w + b.x + b.y + b.z + b.w
                          + c.x + c.y + c.z + c.w + d.x + d.y + d.z + d.w;
        ss[tid] = part;
        __syncthreads();
        for (int off = 1; off < 512; off <<= 1) {
            unsigned int v = (tid + off < 512) ? ss[tid + off] : 0u;
            __syncthreads();
            ss[tid] += v;
            __syncthreads();
        }
        unsigned int incl = ss[tid];
        unsigned int nxt = (tid < 511) ? ss[tid + 1] : 0u;
        if (incl >= KTOP && nxt < KTOP) {
            unsigned int acc = nxt;
            for (int bi = tid * 16 + 15; bi >= tid * 16; bi--) {
                acc += g_hist[bi];
                if (acc >= KTOP) { s_tbin = (unsigned int)bi; break; }
            }
        }
        __syncthreads();
    }

    // ---- phase 3: compact candidates (whole grid, one float4/thread) ----
    {
        unsigned int tb = s_tbin;
        int n4 = n >> 2;
        const float4* __restrict__ y4 = reinterpret_cast<const float4*>(g_y);
        for (int i = gtid; i < n4; i += gthreads) {
            float4 v = y4[i];
            try_push(v.x, i * 4 + 0, tb);
            try_push(v.y, i * 4 + 1, tb);
            try_push(v.z, i * 4 + 2, tb);
            try_push(v.w, i * 4 + 3, tb);
        }
        if (gtid == 0) {
            for (int j = n & ~3; j < n; j++) try_push(g_y[j], j, tb);
        }
    }
    grid_bar(nb);

    // ---- phase 4: exact rank; 64 candidates/block x 8 segments ----
    {
        int C = (int)min(g_cnt, (unsigned int)CAND_MAX);
        int nactive = (C + 63) >> 6;
        if (blockIdx.x < nactive) {
            for (int i = tid; i < C; i += TPB) sk[i] = g_cand[i];
            __syncthreads();
            int j = tid & 63;          // candidate slot within block
            int seg = tid >> 6;        // segment 0..7
            int jg = blockIdx.x * 64 + j;
            unsigned long long pk = (jg < C) ? sk[jg] : ~0ull;
            int segsz = (C + 7) >> 3;
            int lo = seg * segsz;
            int hi = lo + segsz; if (hi > C) hi = C;
            int part = 0;
            int i = lo;
            for (; i + 4 <= hi; i += 4) {
                part += (sk[i + 0] > pk);
                part += (sk[i + 1] > pk);
                part += (sk[i + 2] > pk);
                part += (sk[i + 3] > pk);
            }
            for (; i < hi; i++) part += (sk[i] > pk);
            ss[tid] = (unsigned int)part;
            __syncthreads();
            if (tid < 64 && jg < C) {
                int rank = (int)(ss[tid] + ss[tid + 64] + ss[tid + 128] +
                                 ss[tid + 192] + ss[tid + 256] + ss[tid + 320] +
                                 ss[tid + 384] + ss[tid + 448]);
                if (rank < KTOP) {
                    unsigned int key = (unsigned int)(pk >> 32);
                    unsigned int u = (key & 0x80000000u) ? (key ^ 0x80000000u) : ~key;
                    g_tval[rank] = __uint_as_float(u);
                    g_tidx[rank] = (int)(~(unsigned int)(pk & 0xFFFFFFFFull));
                }
            }
        }
    }
    grid_bar(nb);

    // ---- phase 5: gather + tanh; restore global state for next replay ----
    float4* __restrict__ o4 = reinterpret_cast<float4*>(out);
    for (int w = wid; w < KTOP; w += nw) {
        int idx = g_tidx[w];
        float t = tanhf(g_tval[w]);
        float4 v = x4[(size_t)idx * 32 + lane];
        o4[(size_t)w * 32 + lane] = make_float4(v.x * t, v.y * t, v.z * t, v.w * t);
    }
    for (int i = gtid; i < HBINS; i += gthreads) g_hist[i] = 0u;
    if (gtid == 0) g_cnt = 0u;
}

extern "C" void kernel_launch(void* const* d_in, const int* in_sizes, int n_in,
                              void* d_out, int out_size) {
    const float* x = (const float*)d_in[0];
    const float* p = (const float*)d_in[1];
    int n = in_sizes[0] / DD;

    int dev = 0;
    cudaGetDevice(&dev);
    int sm = 0;
    cudaDeviceGetAttribute(&sm, cudaDevAttrMultiProcessorCount, dev);
    int bpsm = 0;
    cudaOccupancyMaxActiveBlocksPerMultiprocessor(&bpsm, mega, TPB, 0);
    if (bpsm < 1) bpsm = 1;
    int nb = sm * bpsm;
    if (nb > NB_CAP) nb = NB_CAP;

    mega<<<nb, TPB>>>(x, p, (float*)d_out, n, nb);
}